// round 13
// baseline (speedup 1.0000x reference)
#include <cuda_runtime.h>

#define Bb 96
#define Tt 48
#define LD 64
#define GD 64
#define MT 10
#define HH 128

#define NT 256
#define SW_F 16384
#define SH1_STRIDE 129
#define SH1_F (48*SH1_STRIDE)
#define LOC_CTAS 576
#define GLB_CTAS 12

typedef unsigned long long ull;

__device__ float g_P[Bb*HH];      // sampled-locals @ gw1[:640] [96,128]
__device__ float g_Q[Bb*HH];      // globals @ gw1[640:] + gb1  [96,128]
__device__ float g_Bg[Bb*HH];     // globals @ lw1[64:] + lb1   [96,128]

__device__ __forceinline__ ull pack2(float lo, float hi){
    ull r; asm("mov.b64 %0, {%1, %2};" : "=l"(r) : "f"(lo), "f"(hi)); return r;
}
__device__ __forceinline__ void fma2(ull &d, ull a, ull b){
    asm("fma.rn.f32x2 %0, %1, %2, %0;" : "+l"(d) : "l"(a), "l"(b));
}
__device__ __forceinline__ float2 unpack2(ull v){
    float2 f; asm("mov.b64 {%0, %1}, %2;" : "=f"(f.x), "=f"(f.y) : "l"(v)); return f;
}

// ---------------------------------------------------------------------------
// Precompute Bg, Q, P per batch-row i.
// ---------------------------------------------------------------------------
__global__ __launch_bounds__(128) void precompute_pqb_kernel(
    const float* __restrict__ globals_, const float* __restrict__ locals_,
    const float* __restrict__ gw1, const float* __restrict__ gb1,
    const float* __restrict__ lw1, const float* __restrict__ lb1,
    const int* __restrict__ idx_t)
{
    __shared__ float lsrow[MT*LD];
    __shared__ float grow[GD];
    __shared__ int   sidx[MT];

    const int i = blockIdx.x;
    const int tid = threadIdx.x;

    if (tid < GD) grow[tid] = globals_[i*GD + tid];
    if (tid < MT) sidx[tid] = idx_t[i*MT + tid];
    __syncthreads();
    for (int idx = tid; idx < MT*LD; idx += 128) {
        int m = idx >> 6, k = idx & 63;
        lsrow[idx] = locals_[(i*Tt + sidx[m])*LD + k];
    }
    __syncthreads();

    const int h = tid;

    float bv = lb1[h];
    for (int k = 0; k < GD; k++) bv += grow[k] * lw1[(LD + k)*HH + h];
    g_Bg[i*HH + h] = bv;

    float qv = gb1[h];
    for (int k = 0; k < GD; k++) qv += grow[k] * gw1[(MT*LD + k)*HH + h];
    g_Q[i*HH + h] = qv;

    float pv = 0.f;
    for (int k = 0; k < MT*LD; k++) pv += lsrow[k] * gw1[k*HH + h];
    g_P[i*HH + h] = pv;
}

// ---------------------------------------------------------------------------
// Unified MI kernel, 2 CTAs/SM (94KB smem). j processed in two 48-halves.
// CTAs [0,576): locals (A-rows computed in prologue); [576,588): globals.
// Geometry per half: 16 jg (3 j) x 16 hg (8 h). fp32 FFMA2 accumulators.
// ---------------------------------------------------------------------------
__global__ void __launch_bounds__(NT, 2) mi_kernel(
    const float* __restrict__ locals_, const float* __restrict__ lw1,
    const float* __restrict__ lw2, const float* __restrict__ lb2,
    const float* __restrict__ lw3, const float* __restrict__ lb3,
    const float* __restrict__ gw2, const float* __restrict__ gb2,
    const float* __restrict__ gw3, const float* __restrict__ gb3,
    float* __restrict__ out_l, float* __restrict__ out_g)
{
    extern __shared__ float sm[];
    float* sw     = sm;                 // [128][128] w2, 64 KB
    float* sh1    = sm + SW_F;          // [48][129]  h1 half-tile (~24.2 KB)
    float* arow8  = sh1 + SH1_F;        // [8][128]   layer-1 left rows (4 KB)

    const int bid = blockIdx.x;
    const bool isg = (bid >= LOC_CTAS);

    const float* w2 = isg ? gw2 : lw2;
    const float* b2 = isg ? gb2 : lb2;
    const float* w3 = isg ? gw3 : lw3;
    const float* b3 = isg ? gb3 : lb3;
    const float* brows = isg ? g_Q : g_Bg;
    float* out = isg ? out_g : out_l;
    const int row0 = (isg ? (bid - LOC_CTAS) : bid) * 8;

    const int tid = threadIdx.x;
    const int jg = tid >> 4;           // 0..15
    const int hg = tid & 15;           // 0..15
    const int hA = hg * 4;
    const int hB = 64 + hg * 4;

    // ---- prologue: w2 -> smem ----
    const float4* w24 = (const float4*)w2;
    float4* sw4 = (float4*)sw;
    for (int idx = tid; idx < SW_F/4; idx += NT) sw4[idx] = w24[idx];

    if (isg) {
        for (int idx = tid; idx < 8*HH; idx += NT)
            arow8[idx] = g_P[row0*HH + idx];
        __syncthreads();
    } else {
        // compute 8 A rows = locals[i, t0..t0+8) @ lw1[0:64]
        const int i  = bid / 6;
        const int t0 = (bid - i*6) * 8;
        float* ltile = sh1;            // reuse sh1 space as [8][64] temp
        for (int idx = tid; idx < 8*LD; idx += NT)
            ltile[idx] = locals_[(i*Tt + t0)*LD + idx];
        __syncthreads();

        const int h  = tid & 127;
        const int tg = tid >> 7;       // 0/1 -> t rows tg, tg+2, tg+4, tg+6
        float a0 = 0.f, a1 = 0.f, a2 = 0.f, a3 = 0.f;
        #pragma unroll 8
        for (int k = 0; k < LD; k++) {
            float w = lw1[k*HH + h];
            a0 += ltile[(tg  )*LD + k] * w;
            a1 += ltile[(tg+2)*LD + k] * w;
            a2 += ltile[(tg+4)*LD + k] * w;
            a3 += ltile[(tg+6)*LD + k] * w;
        }
        __syncthreads();               // ltile reads done before sh1 reuse
        arow8[(tg  )*HH + h] = a0;
        arow8[(tg+2)*HH + h] = a1;
        arow8[(tg+4)*HH + h] = a2;
        arow8[(tg+6)*HH + h] = a3;
        __syncthreads();
    }

    // b2 accumulator init (pairs); w3, b3 in registers
    float2 q0 = *(const float2*)(b2 + hA);
    float2 q1 = *(const float2*)(b2 + hA + 2);
    float2 q2 = *(const float2*)(b2 + hB);
    float2 q3 = *(const float2*)(b2 + hB + 2);
    ull binit[4] = { pack2(q0.x,q0.y), pack2(q1.x,q1.y), pack2(q2.x,q2.y), pack2(q3.x,q3.y) };
    const float b3v = __ldg(b3);
    float4 w3a = *(const float4*)(w3 + hA);
    float4 w3b = *(const float4*)(w3 + hB);

    const longlong2* swq = (const longlong2*)sw;  // pair-pairs: swq[k*32 + h/4]

    for (int r = 0; r < 8; r++) {
        const int row = row0 + r;
        const float* arow = arow8 + r*HH;

        #pragma unroll 1
        for (int half = 0; half < 2; half++) {
            __syncthreads();   // prior k-loop readers done with sh1

            // h1[jl][k] = relu(arow[k] + brows[half*48+jl][k])
            const float* br = brows + half*48*HH;
            for (int idx = tid; idx < 48*HH; idx += NT) {
                int k = idx & 127;
                float v = arow[k] + br[idx];
                sh1[(idx >> 7)*SH1_STRIDE + k] = v > 0.f ? v : 0.f;
            }
            __syncthreads();

            ull acc[3][4];
            #pragma unroll
            for (int jj = 0; jj < 3; jj++) {
                #pragma unroll
                for (int p = 0; p < 4; p++) acc[jj][p] = binit[p];
            }

            const float* a_base = sh1 + (jg*3)*SH1_STRIDE;

            #pragma unroll 4
            for (int k = 0; k < HH; k++) {
                longlong2 wv0 = swq[(k << 5) + hg];        // bf0, bf1
                longlong2 wv1 = swq[(k << 5) + 16 + hg];   // bf2, bf3
                ull bf0 = (ull)wv0.x, bf1 = (ull)wv0.y;
                ull bf2 = (ull)wv1.x, bf3 = (ull)wv1.y;
                #pragma unroll
                for (int jj = 0; jj < 3; jj++) {
                    float a = a_base[jj*SH1_STRIDE + k];
                    ull a2 = pack2(a, a);
                    fma2(acc[jj][0], a2, bf0);
                    fma2(acc[jj][1], a2, bf1);
                    fma2(acc[jj][2], a2, bf2);
                    fma2(acc[jj][3], a2, bf3);
                }
            }

            // Epilogue: relu(h2) . w3, reduce over 16 hg lanes
            #pragma unroll
            for (int jj = 0; jj < 3; jj++) {
                float2 v0 = unpack2(acc[jj][0]);
                float2 v1 = unpack2(acc[jj][1]);
                float2 v2 = unpack2(acc[jj][2]);
                float2 v3 = unpack2(acc[jj][3]);
                float s = fmaxf(v0.x,0.f)*w3a.x + fmaxf(v0.y,0.f)*w3a.y
                        + fmaxf(v1.x,0.f)*w3a.z + fmaxf(v1.y,0.f)*w3a.w
                        + fmaxf(v2.x,0.f)*w3b.x + fmaxf(v2.y,0.f)*w3b.y
                        + fmaxf(v3.x,0.f)*w3b.z + fmaxf(v3.y,0.f)*w3b.w;
                s += __shfl_xor_sync(0xffffffffu, s, 1);
                s += __shfl_xor_sync(0xffffffffu, s, 2);
                s += __shfl_xor_sync(0xffffffffu, s, 4);
                s += __shfl_xor_sync(0xffffffffu, s, 8);
                if (hg == 0) {
                    int j = half*48 + jg*3 + jj;
                    int o;
                    if (!isg) {
                        int ii = row / Tt, tt = row - ii*Tt;
                        o = tt*(Bb*Bb) + ii*Bb + j;      // locals_mi[t][i][j]
                    } else {
                        o = row*Bb + j;                   // globals_mi[i][j]
                    }
                    out[o] = s + b3v;
                }
            }
        }
    }
}

// ---------------------------------------------------------------------------
extern "C" void kernel_launch(void* const* d_in, const int* in_sizes, int n_in,
                              void* d_out, int out_size)
{
    const float* globals_ = (const float*)d_in[0];
    const float* locals_  = (const float*)d_in[1];
    const float* gw1 = (const float*)d_in[2];
    const float* gb1 = (const float*)d_in[3];
    const float* gw2 = (const float*)d_in[4];
    const float* gb2 = (const float*)d_in[5];
    const float* gw3 = (const float*)d_in[6];
    const float* gb3 = (const float*)d_in[7];
    const float* lw1 = (const float*)d_in[8];
    const float* lb1 = (const float*)d_in[9];
    const float* lw2 = (const float*)d_in[10];
    const float* lb2 = (const float*)d_in[11];
    const float* lw3 = (const float*)d_in[12];
    const float* lb3 = (const float*)d_in[13];
    const int*  idx_t = (const int*)d_in[14];

    float* out = (float*)d_out;

    // Pass-through outputs
    cudaMemcpyAsync(out, globals_, (size_t)Bb*GD*sizeof(float),
                    cudaMemcpyDeviceToDevice, 0);
    cudaMemcpyAsync(out + Bb*GD, locals_, (size_t)Bb*Tt*LD*sizeof(float),
                    cudaMemcpyDeviceToDevice, 0);

    precompute_pqb_kernel<<<Bb, 128>>>(globals_, locals_, gw1, gb1, lw1, lb1, idx_t);

    size_t smem = (size_t)(SW_F + SH1_F + 8*HH) * sizeof(float);
    cudaFuncSetAttribute(mi_kernel, cudaFuncAttributeMaxDynamicSharedMemorySize, (int)smem);

    float* gmi = out + (Bb*GD + Bb*Tt*LD);
    float* lmi = gmi + Bb*Bb;

    mi_kernel<<<LOC_CTAS + GLB_CTAS, NT, smem>>>(locals_, lw1,
                                                 lw2, lb2, lw3, lb3,
                                                 gw2, gb2, gw3, gb3,
                                                 lmi, gmi);
}

// round 15
// speedup vs baseline: 1.2524x; 1.2524x over previous
#include <cuda_runtime.h>

#define Bb 96
#define Tt 48
#define LD 64
#define GD 64
#define MT 10
#define HH 128

#define NT 512
#define SW_F 16384
#define SH1_STRIDE 129
#define SH1_F (Bb*SH1_STRIDE)
#define PART_STRIDE 17
#define LOC_CTAS 576
#define GLB_CTAS 12

typedef unsigned long long ull;

__device__ float g_P[Bb*HH];      // sampled-locals @ gw1[:640] [96,128]
__device__ float g_Q[Bb*HH];      // globals @ gw1[640:] + gb1  [96,128]
__device__ float g_Bg[Bb*HH];     // globals @ lw1[64:] + lb1   [96,128]

__device__ __forceinline__ ull pack2(float lo, float hi){
    ull r; asm("mov.b64 %0, {%1, %2};" : "=l"(r) : "f"(lo), "f"(hi)); return r;
}
__device__ __forceinline__ void fma2(ull &d, ull a, ull b){
    asm("fma.rn.f32x2 %0, %1, %2, %0;" : "+l"(d) : "l"(a), "l"(b));
}
__device__ __forceinline__ float2 unpack2(ull v){
    float2 f; asm("mov.b64 {%0, %1}, %2;" : "=f"(f.x), "=f"(f.y) : "l"(v)); return f;
}

// ---------------------------------------------------------------------------
// Precompute Bg, Q, P per batch-row i.
// ---------------------------------------------------------------------------
__global__ __launch_bounds__(128) void precompute_pqb_kernel(
    const float* __restrict__ globals_, const float* __restrict__ locals_,
    const float* __restrict__ gw1, const float* __restrict__ gb1,
    const float* __restrict__ lw1, const float* __restrict__ lb1,
    const int* __restrict__ idx_t)
{
    __shared__ float lsrow[MT*LD];
    __shared__ float grow[GD];
    __shared__ int   sidx[MT];

    const int i = blockIdx.x;
    const int tid = threadIdx.x;

    if (tid < GD) grow[tid] = globals_[i*GD + tid];
    if (tid < MT) sidx[tid] = idx_t[i*MT + tid];
    __syncthreads();
    for (int idx = tid; idx < MT*LD; idx += 128) {
        int m = idx >> 6, k = idx & 63;
        lsrow[idx] = locals_[(i*Tt + sidx[m])*LD + k];
    }
    __syncthreads();

    const int h = tid;

    float bv = lb1[h];
    for (int k = 0; k < GD; k++) bv += grow[k] * lw1[(LD + k)*HH + h];
    g_Bg[i*HH + h] = bv;

    float qv = gb1[h];
    for (int k = 0; k < GD; k++) qv += grow[k] * gw1[(MT*LD + k)*HH + h];
    g_Q[i*HH + h] = qv;

    float pv = 0.f;
    for (int k = 0; k < MT*LD; k++) pv += lsrow[k] * gw1[k*HH + h];
    g_P[i*HH + h] = pv;
}

// ---------------------------------------------------------------------------
// Unified MI kernel, broadcast-w2 geometry. 512 threads, 1 CTA/SM.
// Warp w owns h-block [w*8, w*8+8); lane = j within each of 3 j-blocks of 32.
// w2 loads are warp-uniform (broadcast, 1 phase); h1 gathers are stride-129
// conflict-free. CTAs [0,576): locals (A-rows in prologue); rest: globals.
// ---------------------------------------------------------------------------
__global__ void __launch_bounds__(NT, 1) mi_kernel(
    const float* __restrict__ locals_, const float* __restrict__ lw1,
    const float* __restrict__ lw2, const float* __restrict__ lb2,
    const float* __restrict__ lw3, const float* __restrict__ lb3,
    const float* __restrict__ gw2, const float* __restrict__ gb2,
    const float* __restrict__ gw3, const float* __restrict__ gb3,
    float* __restrict__ out_l, float* __restrict__ out_g)
{
    extern __shared__ float sm[];
    float* sw     = sm;                 // [128][128] w2, 64 KB
    float* sh1    = sm + SW_F;          // [96][129]  h1 tile
    float* arow8  = sh1 + SH1_F;        // [8][128]   layer-1 left rows
    float* parts  = arow8 + 8*HH;       // [96][17]   h-block partials

    const int bid = blockIdx.x;
    const bool isg = (bid >= LOC_CTAS);

    const float* w2 = isg ? gw2 : lw2;
    const float* b2 = isg ? gb2 : lb2;
    const float* w3 = isg ? gw3 : lw3;
    const float* b3 = isg ? gb3 : lb3;
    const float* brows = isg ? g_Q : g_Bg;
    float* out = isg ? out_g : out_l;
    const int row0 = (isg ? (bid - LOC_CTAS) : bid) * 8;

    const int tid  = threadIdx.x;
    const int wid  = tid >> 5;         // 0..15  -> h block
    const int lane = tid & 31;         // j within block
    const int h0   = wid * 8;

    // ---- prologue: w2 -> smem ----
    const float4* w24 = (const float4*)w2;
    float4* sw4 = (float4*)sw;
    for (int idx = tid; idx < SW_F/4; idx += NT) sw4[idx] = w24[idx];

    if (isg) {
        for (int idx = tid; idx < 8*HH; idx += NT)
            arow8[idx] = g_P[row0*HH + idx];
        __syncthreads();
    } else {
        // compute 8 A rows = locals[i, t0..t0+8) @ lw1[0:64]
        const int i  = bid / 6;
        const int t0 = (bid - i*6) * 8;
        float* ltile = sh1;            // reuse sh1 space as [8][64] temp
        for (int idx = tid; idx < 8*LD; idx += NT)
            ltile[idx] = locals_[(i*Tt + t0)*LD + idx];
        __syncthreads();

        const int h  = tid & 127;
        const int tg = tid >> 7;       // 0..3 -> rows tg, tg+4
        float a0 = 0.f, a1 = 0.f;
        #pragma unroll 8
        for (int k = 0; k < LD; k++) {
            float w = lw1[k*HH + h];
            a0 += ltile[(tg  )*LD + k] * w;
            a1 += ltile[(tg+4)*LD + k] * w;
        }
        __syncthreads();               // ltile reads done before sh1 reuse
        arow8[(tg  )*HH + h] = a0;
        arow8[(tg+4)*HH + h] = a1;
        __syncthreads();
    }

    // b2 accumulator init (pairs for h0..h0+7); w3, b3 in registers
    float2 q0 = *(const float2*)(b2 + h0);
    float2 q1 = *(const float2*)(b2 + h0 + 2);
    float2 q2 = *(const float2*)(b2 + h0 + 4);
    float2 q3 = *(const float2*)(b2 + h0 + 6);
    ull binit[4] = { pack2(q0.x,q0.y), pack2(q1.x,q1.y), pack2(q2.x,q2.y), pack2(q3.x,q3.y) };
    const float b3v = __ldg(b3);
    float4 w3lo = *(const float4*)(w3 + h0);
    float4 w3hi = *(const float4*)(w3 + h0 + 4);

    for (int r = 0; r < 8; r++) {
        const int row = row0 + r;
        const float* arow = arow8 + r*HH;

        __syncthreads();   // prior iter k-loop + parts reads done

        // h1[j][k] = relu(arow[k] + brows[j][k])
        for (int idx = tid; idx < Bb*HH; idx += NT) {
            int k = idx & 127;
            float v = arow[k] + brows[idx];
            sh1[(idx >> 7)*SH1_STRIDE + k] = v > 0.f ? v : 0.f;
        }
        __syncthreads();

        ull acc[3][4];
        #pragma unroll
        for (int jb = 0; jb < 3; jb++) {
            #pragma unroll
            for (int p = 0; p < 4; p++) acc[jb][p] = binit[p];
        }

        const float* abase = sh1 + lane*SH1_STRIDE;

        #pragma unroll 4
        for (int k = 0; k < HH; k++) {
            // warp-uniform w2 loads (broadcast): w2[k][h0..h0+7]
            const longlong2* swq = (const longlong2*)(sw + (k << 7) + h0);
            longlong2 wq0 = swq[0];
            longlong2 wq1 = swq[1];
            ull bf0 = (ull)wq0.x, bf1 = (ull)wq0.y;
            ull bf2 = (ull)wq1.x, bf3 = (ull)wq1.y;
            #pragma unroll
            for (int jb = 0; jb < 3; jb++) {
                float a = abase[jb*(32*SH1_STRIDE) + k];
                ull a2 = pack2(a, a);
                fma2(acc[jb][0], a2, bf0);
                fma2(acc[jb][1], a2, bf1);
                fma2(acc[jb][2], a2, bf2);
                fma2(acc[jb][3], a2, bf3);
            }
        }

        // Epilogue: relu(h2).w3 partial per (j, h-block)
        #pragma unroll
        for (int jb = 0; jb < 3; jb++) {
            float2 v0 = unpack2(acc[jb][0]);
            float2 v1 = unpack2(acc[jb][1]);
            float2 v2 = unpack2(acc[jb][2]);
            float2 v3 = unpack2(acc[jb][3]);
            float s = fmaxf(v0.x,0.f)*w3lo.x + fmaxf(v0.y,0.f)*w3lo.y
                    + fmaxf(v1.x,0.f)*w3lo.z + fmaxf(v1.y,0.f)*w3lo.w
                    + fmaxf(v2.x,0.f)*w3hi.x + fmaxf(v2.y,0.f)*w3hi.y
                    + fmaxf(v3.x,0.f)*w3hi.z + fmaxf(v3.y,0.f)*w3hi.w;
            parts[(jb*32 + lane)*PART_STRIDE + wid] = s;
        }
        __syncthreads();

        if (tid < Bb) {
            float s = b3v;
            #pragma unroll
            for (int w = 0; w < 16; w++) s += parts[tid*PART_STRIDE + w];
            int o;
            if (!isg) {
                int ii = row / Tt, tt = row - ii*Tt;
                o = tt*(Bb*Bb) + ii*Bb + tid;        // locals_mi[t][i][j]
            } else {
                o = row*Bb + tid;                     // globals_mi[i][j]
            }
            out[o] = s;
        }
    }
}

// ---------------------------------------------------------------------------
extern "C" void kernel_launch(void* const* d_in, const int* in_sizes, int n_in,
                              void* d_out, int out_size)
{
    const float* globals_ = (const float*)d_in[0];
    const float* locals_  = (const float*)d_in[1];
    const float* gw1 = (const float*)d_in[2];
    const float* gb1 = (const float*)d_in[3];
    const float* gw2 = (const float*)d_in[4];
    const float* gb2 = (const float*)d_in[5];
    const float* gw3 = (const float*)d_in[6];
    const float* gb3 = (const float*)d_in[7];
    const float* lw1 = (const float*)d_in[8];
    const float* lb1 = (const float*)d_in[9];
    const float* lw2 = (const float*)d_in[10];
    const float* lb2 = (const float*)d_in[11];
    const float* lw3 = (const float*)d_in[12];
    const float* lb3 = (const float*)d_in[13];
    const int*  idx_t = (const int*)d_in[14];

    float* out = (float*)d_out;

    // Pass-through outputs
    cudaMemcpyAsync(out, globals_, (size_t)Bb*GD*sizeof(float),
                    cudaMemcpyDeviceToDevice, 0);
    cudaMemcpyAsync(out + Bb*GD, locals_, (size_t)Bb*Tt*LD*sizeof(float),
                    cudaMemcpyDeviceToDevice, 0);

    precompute_pqb_kernel<<<Bb, 128>>>(globals_, locals_, gw1, gb1, lw1, lb1, idx_t);

    size_t smem = (size_t)(SW_F + SH1_F + 8*HH + Bb*PART_STRIDE) * sizeof(float);
    cudaFuncSetAttribute(mi_kernel, cudaFuncAttributeMaxDynamicSharedMemorySize, (int)smem);

    float* gmi = out + (Bb*GD + Bb*Tt*LD);
    float* lmi = gmi + Bb*Bb;

    mi_kernel<<<LOC_CTAS + GLB_CTAS, NT, smem>>>(locals_, lw1,
                                                 lw2, lb2, lw3, lb3,
                                                 gw2, gb2, gw3, gb3,
                                                 lmi, gmi);
}

// round 16
// speedup vs baseline: 1.2598x; 1.0059x over previous
#include <cuda_runtime.h>

#define Bb 96
#define Tt 48
#define LD 64
#define GD 64
#define MT 10
#define HH 128

#define NT 512
#define SW_F 16384
#define SH1_STRIDE 132
#define SH1_F (Bb*SH1_STRIDE)
#define PART_STRIDE 17
#define LOC_CTAS 576
#define GLB_CTAS 12

typedef unsigned long long ull;

__device__ float g_P[Bb*HH];      // sampled-locals @ gw1[:640] [96,128]
__device__ float g_Q[Bb*HH];      // globals @ gw1[640:] + gb1  [96,128]
__device__ float g_Bg[Bb*HH];     // globals @ lw1[64:] + lb1   [96,128]

__device__ __forceinline__ ull pack2(float lo, float hi){
    ull r; asm("mov.b64 %0, {%1, %2};" : "=l"(r) : "f"(lo), "f"(hi)); return r;
}
__device__ __forceinline__ void fma2(ull &d, ull a, ull b){
    asm("fma.rn.f32x2 %0, %1, %2, %0;" : "+l"(d) : "l"(a), "l"(b));
}
__device__ __forceinline__ float2 unpack2(ull v){
    float2 f; asm("mov.b64 {%0, %1}, %2;" : "=f"(f.x), "=f"(f.y) : "l"(v)); return f;
}

// ---------------------------------------------------------------------------
// Precompute Bg, Q, P per batch-row i.
// ---------------------------------------------------------------------------
__global__ __launch_bounds__(128) void precompute_pqb_kernel(
    const float* __restrict__ globals_, const float* __restrict__ locals_,
    const float* __restrict__ gw1, const float* __restrict__ gb1,
    const float* __restrict__ lw1, const float* __restrict__ lb1,
    const int* __restrict__ idx_t)
{
    __shared__ float lsrow[MT*LD];
    __shared__ float grow[GD];
    __shared__ int   sidx[MT];

    const int i = blockIdx.x;
    const int tid = threadIdx.x;

    if (tid < GD) grow[tid] = globals_[i*GD + tid];
    if (tid < MT) sidx[tid] = idx_t[i*MT + tid];
    __syncthreads();
    for (int idx = tid; idx < MT*LD; idx += 128) {
        int m = idx >> 6, k = idx & 63;
        lsrow[idx] = locals_[(i*Tt + sidx[m])*LD + k];
    }
    __syncthreads();

    const int h = tid;

    float bv = lb1[h];
    for (int k = 0; k < GD; k++) bv += grow[k] * lw1[(LD + k)*HH + h];
    g_Bg[i*HH + h] = bv;

    float qv = gb1[h];
    for (int k = 0; k < GD; k++) qv += grow[k] * gw1[(MT*LD + k)*HH + h];
    g_Q[i*HH + h] = qv;

    float pv = 0.f;
    for (int k = 0; k < MT*LD; k++) pv += lsrow[k] * gw1[k*HH + h];
    g_P[i*HH + h] = pv;
}

// ---------------------------------------------------------------------------
// Unified MI kernel, broadcast-w2 geometry, 4k-batched inner loop.
// Warp w owns h-block [w*8, w*8+8); lane = j within 3 j-blocks of 32.
// w2 loads warp-uniform (broadcast); h1 loads are float4-over-k, stride-132
// rows => conflict-free quarter-warp phases. 512 threads, 1 CTA/SM.
// CTAs [0,576): locals (A-rows in prologue); [576,588): globals.
// ---------------------------------------------------------------------------
__global__ void __launch_bounds__(NT, 1) mi_kernel(
    const float* __restrict__ locals_, const float* __restrict__ lw1,
    const float* __restrict__ lw2, const float* __restrict__ lb2,
    const float* __restrict__ lw3, const float* __restrict__ lb3,
    const float* __restrict__ gw2, const float* __restrict__ gb2,
    const float* __restrict__ gw3, const float* __restrict__ gb3,
    float* __restrict__ out_l, float* __restrict__ out_g)
{
    extern __shared__ float sm[];
    float* sw     = sm;                 // [128][128] w2, 64 KB
    float* sh1    = sm + SW_F;          // [96][132]  h1 tile (16B-aligned rows)
    float* arow8  = sh1 + SH1_F;        // [8][128]   layer-1 left rows
    float* parts  = arow8 + 8*HH;       // [96][17]   h-block partials

    const int bid = blockIdx.x;
    const bool isg = (bid >= LOC_CTAS);

    const float* w2 = isg ? gw2 : lw2;
    const float* b2 = isg ? gb2 : lb2;
    const float* w3 = isg ? gw3 : lw3;
    const float* b3 = isg ? gb3 : lb3;
    const float* brows = isg ? g_Q : g_Bg;
    float* out = isg ? out_g : out_l;
    const int row0 = (isg ? (bid - LOC_CTAS) : bid) * 8;

    const int tid  = threadIdx.x;
    const int wid  = tid >> 5;         // 0..15  -> h block
    const int lane = tid & 31;         // j within block
    const int h0   = wid * 8;

    // ---- prologue: w2 -> smem ----
    const float4* w24 = (const float4*)w2;
    float4* sw4 = (float4*)sw;
    for (int idx = tid; idx < SW_F/4; idx += NT) sw4[idx] = w24[idx];

    if (isg) {
        for (int idx = tid; idx < 8*HH; idx += NT)
            arow8[idx] = g_P[row0*HH + idx];
        __syncthreads();
    } else {
        // compute 8 A rows = locals[i, t0..t0+8) @ lw1[0:64]
        const int i  = bid / 6;
        const int t0 = (bid - i*6) * 8;
        float* ltile = sh1;            // reuse sh1 space as [8][64] temp
        for (int idx = tid; idx < 8*LD; idx += NT)
            ltile[idx] = locals_[(i*Tt + t0)*LD + idx];
        __syncthreads();

        const int h  = tid & 127;
        const int tg = tid >> 7;       // 0..3 -> rows tg, tg+4
        float a0 = 0.f, a1 = 0.f;
        #pragma unroll 8
        for (int k = 0; k < LD; k++) {
            float w = lw1[k*HH + h];
            a0 += ltile[(tg  )*LD + k] * w;
            a1 += ltile[(tg+4)*LD + k] * w;
        }
        __syncthreads();               // ltile reads done before sh1 reuse
        arow8[(tg  )*HH + h] = a0;
        arow8[(tg+4)*HH + h] = a1;
        __syncthreads();
    }

    // b2 accumulator init (pairs for h0..h0+7); w3, b3 in registers
    float2 q0 = *(const float2*)(b2 + h0);
    float2 q1 = *(const float2*)(b2 + h0 + 2);
    float2 q2 = *(const float2*)(b2 + h0 + 4);
    float2 q3 = *(const float2*)(b2 + h0 + 6);
    ull binit[4] = { pack2(q0.x,q0.y), pack2(q1.x,q1.y), pack2(q2.x,q2.y), pack2(q3.x,q3.y) };
    const float b3v = __ldg(b3);
    float4 w3lo = *(const float4*)(w3 + h0);
    float4 w3hi = *(const float4*)(w3 + h0 + 4);

    for (int r = 0; r < 8; r++) {
        const int row = row0 + r;
        const float* arow = arow8 + r*HH;

        __syncthreads();   // prior iter k-loop + parts reads done

        // h1[j][k] = relu(arow[k] + brows[j][k])
        for (int idx = tid; idx < Bb*HH; idx += NT) {
            int k = idx & 127;
            float v = arow[k] + brows[idx];
            sh1[(idx >> 7)*SH1_STRIDE + k] = v > 0.f ? v : 0.f;
        }
        __syncthreads();

        ull acc[3][4];
        #pragma unroll
        for (int jb = 0; jb < 3; jb++) {
            #pragma unroll
            for (int p = 0; p < 4; p++) acc[jb][p] = binit[p];
        }

        const float* abase = sh1 + lane*SH1_STRIDE;

        #pragma unroll 1
        for (int k4 = 0; k4 < HH/4; k4++) {
            const int k = k4 * 4;

            // h1: one float4 per j-block (3 LDS.128, conflict-free)
            float4 a4[3];
            #pragma unroll
            for (int jb = 0; jb < 3; jb++)
                a4[jb] = *(const float4*)(abase + jb*(32*SH1_STRIDE) + k);

            #pragma unroll
            for (int kk = 0; kk < 4; kk++) {
                // warp-uniform w2 loads (broadcast): w2[k+kk][h0..h0+7]
                const longlong2* swq = (const longlong2*)(sw + ((k + kk) << 7) + h0);
                longlong2 wq0 = swq[0];
                longlong2 wq1 = swq[1];
                ull bf0 = (ull)wq0.x, bf1 = (ull)wq0.y;
                ull bf2 = (ull)wq1.x, bf3 = (ull)wq1.y;
                #pragma unroll
                for (int jb = 0; jb < 3; jb++) {
                    float a = (kk == 0) ? a4[jb].x : (kk == 1) ? a4[jb].y
                            : (kk == 2) ? a4[jb].z : a4[jb].w;
                    ull a2 = pack2(a, a);
                    fma2(acc[jb][0], a2, bf0);
                    fma2(acc[jb][1], a2, bf1);
                    fma2(acc[jb][2], a2, bf2);
                    fma2(acc[jb][3], a2, bf3);
                }
            }
        }

        // Epilogue: relu(h2).w3 partial per (j, h-block)
        #pragma unroll
        for (int jb = 0; jb < 3; jb++) {
            float2 v0 = unpack2(acc[jb][0]);
            float2 v1 = unpack2(acc[jb][1]);
            float2 v2 = unpack2(acc[jb][2]);
            float2 v3 = unpack2(acc[jb][3]);
            float s = fmaxf(v0.x,0.f)*w3lo.x + fmaxf(v0.y,0.f)*w3lo.y
                    + fmaxf(v1.x,0.f)*w3lo.z + fmaxf(v1.y,0.f)*w3lo.w
                    + fmaxf(v2.x,0.f)*w3hi.x + fmaxf(v2.y,0.f)*w3hi.y
                    + fmaxf(v3.x,0.f)*w3hi.z + fmaxf(v3.y,0.f)*w3hi.w;
            parts[(jb*32 + lane)*PART_STRIDE + wid] = s;
        }
        __syncthreads();

        if (tid < Bb) {
            float s = b3v;
            #pragma unroll
            for (int w = 0; w < 16; w++) s += parts[tid*PART_STRIDE + w];
            int o;
            if (!isg) {
                int ii = row / Tt, tt = row - ii*Tt;
                o = tt*(Bb*Bb) + ii*Bb + tid;        // locals_mi[t][i][j]
            } else {
                o = row*Bb + tid;                     // globals_mi[i][j]
            }
            out[o] = s;
        }
    }
}

// ---------------------------------------------------------------------------
extern "C" void kernel_launch(void* const* d_in, const int* in_sizes, int n_in,
                              void* d_out, int out_size)
{
    const float* globals_ = (const float*)d_in[0];
    const float* locals_  = (const float*)d_in[1];
    const float* gw1 = (const float*)d_in[2];
    const float* gb1 = (const float*)d_in[3];
    const float* gw2 = (const float*)d_in[4];
    const float* gb2 = (const float*)d_in[5];
    const float* gw3 = (const float*)d_in[6];
    const float* gb3 = (const float*)d_in[7];
    const float* lw1 = (const float*)d_in[8];
    const float* lb1 = (const float*)d_in[9];
    const float* lw2 = (const float*)d_in[10];
    const float* lb2 = (const float*)d_in[11];
    const float* lw3 = (const float*)d_in[12];
    const float* lb3 = (const float*)d_in[13];
    const int*  idx_t = (const int*)d_in[14];

    float* out = (float*)d_out;

    // Pass-through outputs
    cudaMemcpyAsync(out, globals_, (size_t)Bb*GD*sizeof(float),
                    cudaMemcpyDeviceToDevice, 0);
    cudaMemcpyAsync(out + Bb*GD, locals_, (size_t)Bb*Tt*LD*sizeof(float),
                    cudaMemcpyDeviceToDevice, 0);

    precompute_pqb_kernel<<<Bb, 128>>>(globals_, locals_, gw1, gb1, lw1, lb1, idx_t);

    size_t smem = (size_t)(SW_F + SH1_F + 8*HH + Bb*PART_STRIDE) * sizeof(float);
    cudaFuncSetAttribute(mi_kernel, cudaFuncAttributeMaxDynamicSharedMemorySize, (int)smem);

    float* gmi = out + (Bb*GD + Bb*Tt*LD);
    float* lmi = gmi + Bb*Bb;

    mi_kernel<<<LOC_CTAS + GLB_CTAS, NT, smem>>>(locals_, lw1,
                                                 lw2, lb2, lw3, lb3,
                                                 gw2, gb2, gw3, gb3,
                                                 lmi, gmi);
}

// round 17
// speedup vs baseline: 1.2683x; 1.0068x over previous
#include <cuda_runtime.h>

#define Bb 96
#define Tt 48
#define LD 64
#define GD 64
#define MT 10
#define HH 128

#define NT 512
#define SW_F 16384
#define SH1_STRIDE 132
#define SH1_F (Bb*SH1_STRIDE)
#define PART_STRIDE 17
#define LOC_CTAS 576
#define GLB_CTAS 12

typedef unsigned long long ull;

__device__ float g_P[Bb*HH];      // sampled-locals @ gw1[:640] [96,128]
__device__ float g_Q[Bb*HH];      // globals @ gw1[640:] + gb1  [96,128]
__device__ float g_Bg[Bb*HH];     // globals @ lw1[64:] + lb1   [96,128]

__device__ __forceinline__ ull pack2(float lo, float hi){
    ull r; asm("mov.b64 %0, {%1, %2};" : "=l"(r) : "f"(lo), "f"(hi)); return r;
}
__device__ __forceinline__ void fma2(ull &d, ull a, ull b){
    asm("fma.rn.f32x2 %0, %1, %2, %0;" : "+l"(d) : "l"(a), "l"(b));
}
__device__ __forceinline__ float2 unpack2(ull v){
    float2 f; asm("mov.b64 {%0, %1}, %2;" : "=f"(f.x), "=f"(f.y) : "l"(v)); return f;
}

// ---------------------------------------------------------------------------
// Precompute Bg, Q, P per batch-row i.
// ---------------------------------------------------------------------------
__global__ __launch_bounds__(128) void precompute_pqb_kernel(
    const float* __restrict__ globals_, const float* __restrict__ locals_,
    const float* __restrict__ gw1, const float* __restrict__ gb1,
    const float* __restrict__ lw1, const float* __restrict__ lb1,
    const int* __restrict__ idx_t)
{
    __shared__ float lsrow[MT*LD];
    __shared__ float grow[GD];
    __shared__ int   sidx[MT];

    const int i = blockIdx.x;
    const int tid = threadIdx.x;

    if (tid < GD) grow[tid] = globals_[i*GD + tid];
    if (tid < MT) sidx[tid] = idx_t[i*MT + tid];
    __syncthreads();
    for (int idx = tid; idx < MT*LD; idx += 128) {
        int m = idx >> 6, k = idx & 63;
        lsrow[idx] = locals_[(i*Tt + sidx[m])*LD + k];
    }
    __syncthreads();

    const int h = tid;

    float bv = lb1[h];
    for (int k = 0; k < GD; k++) bv += grow[k] * lw1[(LD + k)*HH + h];
    g_Bg[i*HH + h] = bv;

    float qv = gb1[h];
    for (int k = 0; k < GD; k++) qv += grow[k] * gw1[(MT*LD + k)*HH + h];
    g_Q[i*HH + h] = qv;

    float pv = 0.f;
    for (int k = 0; k < MT*LD; k++) pv += lsrow[k] * gw1[k*HH + h];
    g_P[i*HH + h] = pv;
}

// ---------------------------------------------------------------------------
// Unified MI kernel, broadcast-w2 geometry, double-buffered h1 prefetch.
// Warp w owns h-block [w*8, w*8+8); lane = j within 3 j-blocks of 32.
// 512 threads, 1 CTA/SM. CTAs [0,576): locals; [576,588): globals.
// ---------------------------------------------------------------------------
__global__ void __launch_bounds__(NT, 1) mi_kernel(
    const float* __restrict__ locals_, const float* __restrict__ lw1,
    const float* __restrict__ lw2, const float* __restrict__ lb2,
    const float* __restrict__ lw3, const float* __restrict__ lb3,
    const float* __restrict__ gw2, const float* __restrict__ gb2,
    const float* __restrict__ gw3, const float* __restrict__ gb3,
    float* __restrict__ out_l, float* __restrict__ out_g)
{
    extern __shared__ float sm[];
    float* sw     = sm;                 // [128][128] w2, 64 KB
    float* sh1    = sm + SW_F;          // [96][132]  h1 tile
    float* arow8  = sh1 + SH1_F;        // [8][128]   layer-1 left rows
    float* parts  = arow8 + 8*HH;       // [96][17]   h-block partials
    float* b2s    = parts + Bb*PART_STRIDE;  // [128]
    float* w3s    = b2s + HH;                // [128]

    const int bid = blockIdx.x;
    const bool isg = (bid >= LOC_CTAS);

    const float* w2 = isg ? gw2 : lw2;
    const float* b2 = isg ? gb2 : lb2;
    const float* w3 = isg ? gw3 : lw3;
    const float* b3 = isg ? gb3 : lb3;
    const float* brows = isg ? g_Q : g_Bg;
    float* out = isg ? out_g : out_l;
    const int row0 = (isg ? (bid - LOC_CTAS) : bid) * 8;

    const int tid  = threadIdx.x;
    const int wid  = tid >> 5;         // 0..15  -> h block
    const int lane = tid & 31;         // j within block
    const int h0   = wid * 8;

    // ---- prologue: w2 -> smem; b2/w3 -> smem ----
    const float4* w24 = (const float4*)w2;
    float4* sw4 = (float4*)sw;
    for (int idx = tid; idx < SW_F/4; idx += NT) sw4[idx] = w24[idx];
    if (tid < HH){ b2s[tid] = b2[tid]; w3s[tid] = w3[tid]; }

    if (isg) {
        for (int idx = tid; idx < 8*HH; idx += NT)
            arow8[idx] = g_P[row0*HH + idx];
        __syncthreads();
    } else {
        // compute 8 A rows = locals[i, t0..t0+8) @ lw1[0:64]
        const int i  = bid / 6;
        const int t0 = (bid - i*6) * 8;
        float* ltile = sh1;            // reuse sh1 space as [8][64] temp
        for (int idx = tid; idx < 8*LD; idx += NT)
            ltile[idx] = locals_[(i*Tt + t0)*LD + idx];
        __syncthreads();

        const int h  = tid & 127;
        const int tg = tid >> 7;       // 0..3 -> rows tg, tg+4
        float a0 = 0.f, a1 = 0.f;
        #pragma unroll 8
        for (int k = 0; k < LD; k++) {
            float w = lw1[k*HH + h];
            a0 += ltile[(tg  )*LD + k] * w;
            a1 += ltile[(tg+4)*LD + k] * w;
        }
        __syncthreads();               // ltile reads done before sh1 reuse
        arow8[(tg  )*HH + h] = a0;
        arow8[(tg+4)*HH + h] = a1;
        __syncthreads();
    }

    const float b3v = __ldg(b3);

    for (int r = 0; r < 8; r++) {
        const int row = row0 + r;
        const float* arow = arow8 + r*HH;

        __syncthreads();   // prior iter k-loop + parts reads done

        // h1[j][k] = relu(arow[k] + brows[j][k])
        for (int idx = tid; idx < Bb*HH; idx += NT) {
            int k = idx & 127;
            float v = arow[k] + brows[idx];
            sh1[(idx >> 7)*SH1_STRIDE + k] = v > 0.f ? v : 0.f;
        }
        __syncthreads();

        // acc init from b2 (broadcast LDS.64 x4)
        ull acc[3][4];
        {
            const ull* b2p = (const ull*)(b2s + h0);
            #pragma unroll
            for (int p = 0; p < 4; p++) {
                ull bi = b2p[p];
                acc[0][p] = bi; acc[1][p] = bi; acc[2][p] = bi;
            }
        }

        const float* abase = sh1 + lane*SH1_STRIDE;

        // double-buffered h1 prefetch
        float4 a4b[2][3];
        #pragma unroll
        for (int jb = 0; jb < 3; jb++)
            a4b[0][jb] = *(const float4*)(abase + jb*(32*SH1_STRIDE));

        #pragma unroll 2
        for (int k4 = 0; k4 < HH/4; k4++) {
            const int cur = k4 & 1, nxt = cur ^ 1;
            const int k = k4 * 4;

            if (k4 < HH/4 - 1) {
                #pragma unroll
                for (int jb = 0; jb < 3; jb++)
                    a4b[nxt][jb] = *(const float4*)(abase + jb*(32*SH1_STRIDE) + k + 4);
            }

            const longlong2* wp = (const longlong2*)(sw + (k << 7) + h0);

            #pragma unroll
            for (int kk = 0; kk < 4; kk++) {
                longlong2 wq0 = wp[kk*32];
                longlong2 wq1 = wp[kk*32 + 1];
                ull bf0 = (ull)wq0.x, bf1 = (ull)wq0.y;
                ull bf2 = (ull)wq1.x, bf3 = (ull)wq1.y;
                #pragma unroll
                for (int jb = 0; jb < 3; jb++) {
                    float a = (kk == 0) ? a4b[cur][jb].x : (kk == 1) ? a4b[cur][jb].y
                            : (kk == 2) ? a4b[cur][jb].z : a4b[cur][jb].w;
                    ull a2 = pack2(a, a);
                    fma2(acc[jb][0], a2, bf0);
                    fma2(acc[jb][1], a2, bf1);
                    fma2(acc[jb][2], a2, bf2);
                    fma2(acc[jb][3], a2, bf3);
                }
            }
        }

        // Epilogue: relu(h2).w3 partial per (j, h-block)
        float4 w3lo = *(const float4*)(w3s + h0);
        float4 w3hi = *(const float4*)(w3s + h0 + 4);
        #pragma unroll
        for (int jb = 0; jb < 3; jb++) {
            float2 v0 = unpack2(acc[jb][0]);
            float2 v1 = unpack2(acc[jb][1]);
            float2 v2 = unpack2(acc[jb][2]);
            float2 v3 = unpack2(acc[jb][3]);
            float s = fmaxf(v0.x,0.f)*w3lo.x + fmaxf(v0.y,0.f)*w3lo.y
                    + fmaxf(v1.x,0.f)*w3lo.z + fmaxf(v1.y,0.f)*w3lo.w
                    + fmaxf(v2.x,0.f)*w3hi.x + fmaxf(v2.y,0.f)*w3hi.y
                    + fmaxf(v3.x,0.f)*w3hi.z + fmaxf(v3.y,0.f)*w3hi.w;
            parts[(jb*32 + lane)*PART_STRIDE + wid] = s;
        }
        __syncthreads();

        if (tid < Bb) {
            float s = b3v;
            #pragma unroll
            for (int w = 0; w < 16; w++) s += parts[tid*PART_STRIDE + w];
            int o;
            if (!isg) {
                int ii = row / Tt, tt = row - ii*Tt;
                o = tt*(Bb*Bb) + ii*Bb + tid;        // locals_mi[t][i][j]
            } else {
                o = row*Bb + tid;                     // globals_mi[i][j]
            }
            out[o] = s;
        }
    }
}

// ---------------------------------------------------------------------------
extern "C" void kernel_launch(void* const* d_in, const int* in_sizes, int n_in,
                              void* d_out, int out_size)
{
    const float* globals_ = (const float*)d_in[0];
    const float* locals_  = (const float*)d_in[1];
    const float* gw1 = (const float*)d_in[2];
    const float* gb1 = (const float*)d_in[3];
    const float* gw2 = (const float*)d_in[4];
    const float* gb2 = (const float*)d_in[5];
    const float* gw3 = (const float*)d_in[6];
    const float* gb3 = (const float*)d_in[7];
    const float* lw1 = (const float*)d_in[8];
    const float* lb1 = (const float*)d_in[9];
    const float* lw2 = (const float*)d_in[10];
    const float* lb2 = (const float*)d_in[11];
    const float* lw3 = (const float*)d_in[12];
    const float* lb3 = (const float*)d_in[13];
    const int*  idx_t = (const int*)d_in[14];

    float* out = (float*)d_out;

    // Pass-through outputs
    cudaMemcpyAsync(out, globals_, (size_t)Bb*GD*sizeof(float),
                    cudaMemcpyDeviceToDevice, 0);
    cudaMemcpyAsync(out + Bb*GD, locals_, (size_t)Bb*Tt*LD*sizeof(float),
                    cudaMemcpyDeviceToDevice, 0);

    precompute_pqb_kernel<<<Bb, 128>>>(globals_, locals_, gw1, gb1, lw1, lb1, idx_t);

    size_t smem = (size_t)(SW_F + SH1_F + 8*HH + Bb*PART_STRIDE + 2*HH) * sizeof(float);
    cudaFuncSetAttribute(mi_kernel, cudaFuncAttributeMaxDynamicSharedMemorySize, (int)smem);

    float* gmi = out + (Bb*GD + Bb*Tt*LD);
    float* lmi = gmi + Bb*Bb;

    mi_kernel<<<LOC_CTAS + GLB_CTAS, NT, smem>>>(locals_, lw1,
                                                 lw2, lb2, lw3, lb3,
                                                 gw2, gb2, gw3, gb3,
                                                 lmi, gmi);
}